// round 12
// baseline (speedup 1.0000x reference)
#include <cuda_runtime.h>

// ---------------------------------------------------------------------------
// DeepESN on B200 (sm_100a), round 12.
//   drive GEMM: 128x128 tile, 8x8/thread, f32x2-packed (unchanged from R11).
//   recurrence with TWO-GROUP INTERLEAVE:
//     32 batch groups of 8 rows; CTA (gp, sl) handles groups 2gp (phase A)
//     and 2gp+1 (phase B), columns sl*64..+63.  128 CTAs, 1/SM, co-resident.
//     Per step: phase A then phase B. Each phase's cross-CTA barrier was
//     armed one full phase earlier -> spin is near-instant (overhead hidden).
//     Weight slice (64x512) in SMEM shared by both phases.
//     16 warps = 16 k-chunks of 32; lane = 2 cols x 8 rows (acc 8x2 f32x2).
// ---------------------------------------------------------------------------

#define BB   256
#define TT   512
#define UU   512
#define NCLS 10

#define NGRP2 32       // batch groups (8 rows each)
#define BCR2  8        // rows per group
#define NSLC  8        // col slices per group
#define NCOL  64       // cols per slice
#define SSTR  516      // padded k stride
#define RSTR  66       // reduction row stride
#define NTR   512
#define NT    256

// drive GEMM tiling (128x128, k-tile 8)
#define AST2 132
#define BST2 132

__device__ float        g_S0[(size_t)BB * TT * UU];
__device__ float        g_S1[(size_t)BB * TT * UU];
__device__ float        g_U [(size_t)BB * TT * UU];
__device__ float        g_H[3][2][BB * UU];
__device__ float        g_R[BB * 3 * UU];
__device__ unsigned int g_bar[3][NGRP2];

__device__ __forceinline__ void dfma2(unsigned long long& d,
                                      unsigned long long a,
                                      unsigned long long b) {
    asm("fma.rn.f32x2 %0, %1, %2, %0;" : "+l"(d) : "l"(a), "l"(b));
}
__device__ __forceinline__ float dsum2(unsigned long long v) {
    float lo, hi;
    asm("mov.b64 {%0, %1}, %2;" : "=f"(lo), "=f"(hi) : "l"(v));
    return lo + hi;
}
__device__ __forceinline__ unsigned long long pk2(float x) {
    unsigned long long r;
    asm("mov.b64 %0, {%1, %1};" : "=l"(r) : "f"(x));
    return r;
}
__device__ __forceinline__ void upk2(unsigned long long v, float& lo, float& hi) {
    asm("mov.b64 {%0, %1}, %2;" : "=f"(lo), "=f"(hi) : "l"(v));
}

// ============================================================================
// Drive GEMM (unchanged from R11): g_U[M,512] = A[M,K] @ W[K,512] + bias.
// ============================================================================
__global__ void __launch_bounds__(NT)
drive_gemm(const float* __restrict__ x, const float* __restrict__ W,
           const float* __restrict__ bias, int K, int layer, int n_base)
{
    __shared__ float As[8 * AST2];
    __shared__ float Bs[8 * BST2];

    const float* A = (layer == 0) ? x : ((layer == 1) ? g_S0 : g_S1);
    float*       C = g_U;

    const int tid = threadIdx.x;
    const int tx  = tid & 15;
    const int ty  = tid >> 4;
    const int m0  = blockIdx.y * 128;
    const int n0  = n_base + blockIdx.x * 128;

    const int arow  = tid >> 1;
    const int ahalf = tid & 1;
    const int bk    = tid >> 5;
    const int bc4   = tid & 31;

    unsigned long long acc[4][8];
#pragma unroll
    for (int p = 0; p < 4; ++p)
#pragma unroll
        for (int c = 0; c < 8; ++c) acc[p][c] = 0ull;

    for (int kt = 0; kt < K; kt += 8) {
        {
            float4 va = __ldg(reinterpret_cast<const float4*>(
                                  A + (size_t)(m0 + arow) * K + kt + ahalf * 4));
            As[(ahalf * 4 + 0) * AST2 + arow] = va.x;
            As[(ahalf * 4 + 1) * AST2 + arow] = va.y;
            As[(ahalf * 4 + 2) * AST2 + arow] = va.z;
            As[(ahalf * 4 + 3) * AST2 + arow] = va.w;
            float4 vb = __ldg(reinterpret_cast<const float4*>(
                                  W + (size_t)(kt + bk) * UU + n0 + bc4 * 4));
            *reinterpret_cast<float4*>(Bs + bk * BST2 + bc4 * 4) = vb;
        }
        __syncthreads();

#pragma unroll
        for (int k = 0; k < 8; ++k) {
            unsigned long long a[4];
#pragma unroll
            for (int p = 0; p < 4; ++p)
                a[p] = *reinterpret_cast<const unsigned long long*>(
                           As + k * AST2 + ty * 8 + 2 * p);
            float4 b0 = *reinterpret_cast<const float4*>(Bs + k * BST2 + tx * 8);
            float4 b1 = *reinterpret_cast<const float4*>(Bs + k * BST2 + tx * 8 + 4);
            unsigned long long bb[8] = {pk2(b0.x), pk2(b0.y), pk2(b0.z), pk2(b0.w),
                                        pk2(b1.x), pk2(b1.y), pk2(b1.z), pk2(b1.w)};
#pragma unroll
            for (int p = 0; p < 4; ++p)
#pragma unroll
                for (int c = 0; c < 8; ++c)
                    dfma2(acc[p][c], a[p], bb[c]);
        }
        __syncthreads();
    }

    float4 bv0 = __ldg(reinterpret_cast<const float4*>(bias + n0 + tx * 8));
    float4 bv1 = __ldg(reinterpret_cast<const float4*>(bias + n0 + tx * 8 + 4));
    const float bb[8] = {bv0.x, bv0.y, bv0.z, bv0.w, bv1.x, bv1.y, bv1.z, bv1.w};
#pragma unroll
    for (int p = 0; p < 4; ++p) {
        float lo[8], hi[8];
#pragma unroll
        for (int c = 0; c < 8; ++c) {
            upk2(acc[p][c], lo[c], hi[c]);
            lo[c] += bb[c]; hi[c] += bb[c];
        }
        size_t r0 = (size_t)(m0 + ty * 8 + 2 * p) * UU + n0 + tx * 8;
        *reinterpret_cast<float4*>(C + r0)          = make_float4(lo[0], lo[1], lo[2], lo[3]);
        *reinterpret_cast<float4*>(C + r0 + 4)      = make_float4(lo[4], lo[5], lo[6], lo[7]);
        *reinterpret_cast<float4*>(C + r0 + UU)     = make_float4(hi[0], hi[1], hi[2], hi[3]);
        *reinterpret_cast<float4*>(C + r0 + UU + 4) = make_float4(hi[4], hi[5], hi[6], hi[7]);
    }
}

// ============================================================================
// Recurrence with two-group interleave.
// ============================================================================
__global__ void __launch_bounds__(NTR, 1)
recur_kernel(const float* __restrict__ Wrec, int layer)
{
    extern __shared__ float smem[];
    float* sWT  = smem;                        // [64][SSTR] weight slice (shared)
    float* sSt  = smem + NCOL * SSTR;          // [2][8][SSTR] per-phase H rows
    float* sRed = sSt + 2 * BCR2 * SSTR;       // [16*8][RSTR] partials (reused)

    const float* u    = g_U;
    float*       sout = (layer == 0) ? g_S0 : ((layer == 1) ? g_S1 : (float*)0);
    float* const hb0  = g_H[layer][0];
    float* const hb1  = g_H[layer][1];

    const int tid  = threadIdx.x;
    const int lane = tid & 31;
    const int kc   = tid >> 5;                 // warp = k-chunk 0..15 (32 k each)
    const int gp   = blockIdx.x >> 3;          // group pair 0..15
    const int sl   = blockIdx.x & 7;           // col slice
    const int col0 = sl * NCOL;
    const int own0 = sl * 16;                  // own slice in float4 units
    const int kbase = kc * 32;

    const int fi = lane >> 5;                  // unused helper, keep simple
    (void)fi;
    // finalize ownership (tid < 256): row ffi = tid>>5 (0..7), cols (ffj, ffj+32)
    const int ffi = tid >> 5;
    const int ffj = lane;

    // Load transposed weight slice: sWT[c][k] = Wrec[k][col0+c]
    for (int idx = tid; idx < NCOL * UU; idx += NTR) {
        int c = idx & 63, k = idx >> 6;
        sWT[c * SSTR + k] = Wrec[(size_t)k * UU + col0 + c];
    }
    __syncthreads();

    for (int t = 0; t < TT; ++t) {
        const int p = t & 1;
        const float* hsrc = p ? hb1 : hb0;
        float*       hdst = p ? hb0 : hb1;

#pragma unroll 1
        for (int ph = 0; ph < 2; ++ph) {
            const int b0 = gp * 16 + ph * 8;               // this phase's rows
            unsigned int* barp = &g_bar[layer][gp * 2 + ph];
            float* sStP = sSt + ph * BCR2 * SSTR;

            // prefetch u for finalize threads (hidden under spin/stage)
            float u0 = 0.0f, u1 = 0.0f;
            size_t m = 0;
            if (tid < 256) {
                m  = (size_t)(b0 + ffi) * TT + t;
                u0 = __ldg(u + m * UU + col0 + ffj);
                u1 = __ldg(u + m * UU + col0 + ffj + 32);
            }

            // ---- wait (near-instant: target armed one full phase ago) ----
            if (t > 0) {
                if (tid == 0) {
                    const unsigned int tgt = (unsigned int)t * NSLC;
                    unsigned int v;
                    do {
                        asm volatile("ld.acquire.gpu.u32 %0, [%1];"
                                     : "=r"(v) : "l"(barp));
                        if (v >= tgt) break;
                        __nanosleep(32);
                    } while (true);
                }
                __syncthreads();
            }

            // ---- stage this phase's H rows ----
            if (t == 0) {
                for (int idx = tid; idx < BCR2 * 128; idx += NTR) {
                    int i = idx >> 7, c = idx & 127;
                    float4 v = __ldcg(reinterpret_cast<const float4*>(
                                          hsrc + (size_t)(b0 + i) * UU) + c);
                    reinterpret_cast<float4*>(sStP + i * SSTR)[c] = v;
                }
            } else {
                for (int idx = tid; idx < BCR2 * 112; idx += NTR) {
                    int i = idx / 112, c = idx - i * 112;
                    int c4 = (c < own0) ? c : c + 16;
                    float4 v = __ldcg(reinterpret_cast<const float4*>(
                                          hsrc + (size_t)(b0 + i) * UU) + c4);
                    reinterpret_cast<float4*>(sStP + i * SSTR)[c4] = v;
                }
            }
            __syncthreads();

            // ---- matmul: 8 rows x 2 cols per lane over 32-k chunk ----
            unsigned long long acc[8][2];
#pragma unroll
            for (int r = 0; r < 8; ++r) { acc[r][0] = 0ull; acc[r][1] = 0ull; }

            const ulonglong2* w0p = reinterpret_cast<const ulonglong2*>(
                sWT + lane * SSTR + kbase);
            const ulonglong2* w1p = reinterpret_cast<const ulonglong2*>(
                sWT + (lane + 32) * SSTR + kbase);
            const float* arow = sStP + kbase;

#pragma unroll 4
            for (int c = 0; c < 8; ++c) {
                ulonglong2 w0 = w0p[c];
                ulonglong2 w1 = w1p[c];
#pragma unroll
                for (int r = 0; r < 8; ++r) {
                    ulonglong2 a = *reinterpret_cast<const ulonglong2*>(
                        arow + r * SSTR + 4 * c);
                    dfma2(acc[r][0], a.x, w0.x);
                    dfma2(acc[r][0], a.y, w0.y);
                    dfma2(acc[r][1], a.x, w1.x);
                    dfma2(acc[r][1], a.y, w1.y);
                }
            }

            // ---- partials: [kc][r][lane*2 (+1)] ----
            {
                float* base = sRed + (size_t)(kc * BCR2) * RSTR + lane * 2;
#pragma unroll
                for (int r = 0; r < 8; ++r) {
                    float2 v;
                    v.x = dsum2(acc[r][0]);
                    v.y = dsum2(acc[r][1]);
                    *reinterpret_cast<float2*>(base + r * RSTR) = v;
                }
            }
            __syncthreads();

            // ---- finalize (tid < 256): 2 outputs each ----
            if (tid < 256) {
                float z0 = u0, z1 = u1;
                const float* rb = sRed + (size_t)ffi * RSTR + ffj * 2;
#pragma unroll
                for (int k2 = 0; k2 < 16; ++k2) {
                    float2 pv = *reinterpret_cast<const float2*>(
                        rb + (size_t)k2 * (BCR2 * RSTR));
                    z0 += pv.x; z1 += pv.y;
                }
                const float hold0 = sStP[ffi * SSTR + col0 + ffj];
                const float hold1 = sStP[ffi * SSTR + col0 + ffj + 32];
                float hn0 = hold0 * 0.1f + 0.9f * tanhf(z0);
                float hn1 = hold1 * 0.1f + 0.9f * tanhf(z1);
                size_t gh = (size_t)(b0 + ffi) * UU + col0 + ffj;
                hdst[gh]      = hn0;                       // for peer CTAs
                hdst[gh + 32] = hn1;
                sStP[ffi * SSTR + col0 + ffj]      = hn0;  // own-slice carry
                sStP[ffi * SSTR + col0 + ffj + 32] = hn1;
                if (sout) {
                    sout[m * UU + col0 + ffj]      = hn0;
                    sout[m * UU + col0 + ffj + 32] = hn1;
                }
                if (t == TT - 1) {
                    size_t gr = (size_t)(b0 + ffi) * (3 * UU) + layer * UU
                              + col0 + ffj;
                    g_R[gr]      = hn0;
                    g_R[gr + 32] = hn1;
                }
            }

            // ---- arrive (release) ----
            if (t < TT - 1) {
                __syncthreads();
                if (tid == 0) {
                    asm volatile("fence.acq_rel.gpu;" ::: "memory");
                    atomicAdd(barp, 1u);
                }
            }
        }
    }
}

__global__ void init_kernel() {
    int idx = blockIdx.x * blockDim.x + threadIdx.x;
    if (idx < 3 * 2 * BB * UU) ((float*)g_H)[idx] = 0.0f;
    if (idx < 3 * NGRP2) ((unsigned int*)g_bar)[idx] = 0u;
}

__global__ void readout_kernel(const float* __restrict__ Wout,
                               const float* __restrict__ bout,
                               float* __restrict__ out) {
    __shared__ float red[NCLS][NT];
    int b = blockIdx.x, tid = threadIdx.x;
    float part[NCLS];
#pragma unroll
    for (int c = 0; c < NCLS; ++c) part[c] = 0.0f;
    for (int k = tid; k < 3 * UU; k += NT) {
        float r = g_R[(size_t)b * 3 * UU + k];
#pragma unroll
        for (int c = 0; c < NCLS; ++c) part[c] += r * Wout[k * NCLS + c];
    }
#pragma unroll
    for (int c = 0; c < NCLS; ++c) red[c][tid] = part[c];
    __syncthreads();
    if (tid < NCLS) {
        float s = 0.0f;
        for (int i = 0; i < NT; ++i) s += red[tid][i];
        out[b * NCLS + tid] = s + bout[tid];
    }
}

extern "C" void kernel_launch(void* const* d_in, const int* in_sizes, int n_in,
                              void* d_out, int out_size) {
    (void)in_sizes; (void)n_in; (void)out_size;
    const float* x    = (const float*)d_in[0];
    const float* Win0 = (const float*)d_in[1];
    const float* W0   = (const float*)d_in[2];
    const float* b0   = (const float*)d_in[3];
    const float* Win1 = (const float*)d_in[4];
    const float* W1   = (const float*)d_in[5];
    const float* b1   = (const float*)d_in[6];
    const float* Win2 = (const float*)d_in[7];
    const float* W2   = (const float*)d_in[8];
    const float* b2   = (const float*)d_in[9];
    const float* Wout = (const float*)d_in[10];
    const float* bout = (const float*)d_in[11];
    float* out = (float*)d_out;

    // smem: 64x516 + 2x8x516 + 128x66 = 198,912 B
    const int smem = (NCOL * SSTR + 2 * BCR2 * SSTR + 128 * RSTR)
                     * (int)sizeof(float);
    static int attr_done = 0;
    if (!attr_done) {
        cudaFuncSetAttribute(recur_kernel,
                             cudaFuncAttributeMaxDynamicSharedMemorySize, smem);
        attr_done = 1;
    }

    const dim3 ggrid(4, (BB * TT) / 128);
    const dim3 hgrid(2, (BB * TT) / 128);

    init_kernel<<<3072, NT>>>();                             // launch 1
    drive_gemm<<<hgrid, NT>>>(x, Win0, b0, 64, 0, 0);        // launch 2
    drive_gemm<<<hgrid, NT>>>(x, Win0, b0, 64, 0, 256);      // launch 3
    recur_kernel<<<128, NTR, smem>>>(W0, 0);                 // launch 4 (ncu aim)
    drive_gemm<<<ggrid, NT>>>(x, Win1, b1, 512, 1, 0);
    recur_kernel<<<128, NTR, smem>>>(W1, 1);
    drive_gemm<<<ggrid, NT>>>(x, Win2, b2, 512, 2, 0);
    recur_kernel<<<128, NTR, smem>>>(W2, 2);
    readout_kernel<<<BB, NT>>>(Wout, bout, out);
}

// round 13
// speedup vs baseline: 1.0967x; 1.0967x over previous
#include <cuda_runtime.h>

// ---------------------------------------------------------------------------
// DeepESN on B200 (sm_100a), round 13.
//   drive GEMM: 128x128 tile, 8x8/thread, f32x2-packed (unchanged).
//   recurrence: 256 CTAs = 16 batch-groups (16 rows) x 16 col-slices (32 cols)
//     256 threads = 8 warps = 8 k-chunks of 64; lane = 1 col x 16 rows
//     (acc[16] f32x2, k-packed).  SMEM/CTA = 99,072 B -> 2 CTAs/SM: the
//     scheduler overlaps one CTA's barrier/staging/sync overhead with the
//     other CTA's matmul (independent batch groups).  Reduction buffer
//     aliased over the H stage (R10-proven pattern).
//     Monotonic atomic barrier per batch-group (16 arrivals/step).
// ---------------------------------------------------------------------------

#define BB   256
#define TT   512
#define UU   512
#define NCLS 10

// recurrence tiling
#define NGRP 16        // batch groups
#define BCR  16        // rows per group
#define NSL3 16        // col slices per group
#define NCL3 32        // cols per slice
#define SSTR 516       // padded k stride (=4 mod 32 -> conflict-free LDS.128)
#define RST3 33        // reduction slot stride
#define NTR3 256       // threads per recur CTA (8 warps)
#define NT   256

// drive GEMM tiling (128x128, k-tile 8)
#define AST2 132
#define BST2 132

__device__ float        g_S0[(size_t)BB * TT * UU];
__device__ float        g_S1[(size_t)BB * TT * UU];
__device__ float        g_U [(size_t)BB * TT * UU];
__device__ float        g_H[3][2][BB * UU];
__device__ float        g_R[BB * 3 * UU];
__device__ unsigned int g_bar[3][NGRP];

__device__ __forceinline__ void dfma2(unsigned long long& d,
                                      unsigned long long a,
                                      unsigned long long b) {
    asm("fma.rn.f32x2 %0, %1, %2, %0;" : "+l"(d) : "l"(a), "l"(b));
}
__device__ __forceinline__ float dsum2(unsigned long long v) {
    float lo, hi;
    asm("mov.b64 {%0, %1}, %2;" : "=f"(lo), "=f"(hi) : "l"(v));
    return lo + hi;
}
__device__ __forceinline__ unsigned long long pk2(float x) {
    unsigned long long r;
    asm("mov.b64 %0, {%1, %1};" : "=l"(r) : "f"(x));
    return r;
}
__device__ __forceinline__ void upk2(unsigned long long v, float& lo, float& hi) {
    asm("mov.b64 {%0, %1}, %2;" : "=f"(lo), "=f"(hi) : "l"(v));
}

// ============================================================================
// Drive GEMM (unchanged): g_U[M,512] = A[M,K] @ W[K,512] + bias.
// ============================================================================
__global__ void __launch_bounds__(NT)
drive_gemm(const float* __restrict__ x, const float* __restrict__ W,
           const float* __restrict__ bias, int K, int layer, int n_base)
{
    __shared__ float As[8 * AST2];
    __shared__ float Bs[8 * BST2];

    const float* A = (layer == 0) ? x : ((layer == 1) ? g_S0 : g_S1);
    float*       C = g_U;

    const int tid = threadIdx.x;
    const int tx  = tid & 15;
    const int ty  = tid >> 4;
    const int m0  = blockIdx.y * 128;
    const int n0  = n_base + blockIdx.x * 128;

    const int arow  = tid >> 1;
    const int ahalf = tid & 1;
    const int bk    = tid >> 5;
    const int bc4   = tid & 31;

    unsigned long long acc[4][8];
#pragma unroll
    for (int p = 0; p < 4; ++p)
#pragma unroll
        for (int c = 0; c < 8; ++c) acc[p][c] = 0ull;

    for (int kt = 0; kt < K; kt += 8) {
        {
            float4 va = __ldg(reinterpret_cast<const float4*>(
                                  A + (size_t)(m0 + arow) * K + kt + ahalf * 4));
            As[(ahalf * 4 + 0) * AST2 + arow] = va.x;
            As[(ahalf * 4 + 1) * AST2 + arow] = va.y;
            As[(ahalf * 4 + 2) * AST2 + arow] = va.z;
            As[(ahalf * 4 + 3) * AST2 + arow] = va.w;
            float4 vb = __ldg(reinterpret_cast<const float4*>(
                                  W + (size_t)(kt + bk) * UU + n0 + bc4 * 4));
            *reinterpret_cast<float4*>(Bs + bk * BST2 + bc4 * 4) = vb;
        }
        __syncthreads();

#pragma unroll
        for (int k = 0; k < 8; ++k) {
            unsigned long long a[4];
#pragma unroll
            for (int p = 0; p < 4; ++p)
                a[p] = *reinterpret_cast<const unsigned long long*>(
                           As + k * AST2 + ty * 8 + 2 * p);
            float4 b0 = *reinterpret_cast<const float4*>(Bs + k * BST2 + tx * 8);
            float4 b1 = *reinterpret_cast<const float4*>(Bs + k * BST2 + tx * 8 + 4);
            unsigned long long bb[8] = {pk2(b0.x), pk2(b0.y), pk2(b0.z), pk2(b0.w),
                                        pk2(b1.x), pk2(b1.y), pk2(b1.z), pk2(b1.w)};
#pragma unroll
            for (int p = 0; p < 4; ++p)
#pragma unroll
                for (int c = 0; c < 8; ++c)
                    dfma2(acc[p][c], a[p], bb[c]);
        }
        __syncthreads();
    }

    float4 bv0 = __ldg(reinterpret_cast<const float4*>(bias + n0 + tx * 8));
    float4 bv1 = __ldg(reinterpret_cast<const float4*>(bias + n0 + tx * 8 + 4));
    const float bb[8] = {bv0.x, bv0.y, bv0.z, bv0.w, bv1.x, bv1.y, bv1.z, bv1.w};
#pragma unroll
    for (int p = 0; p < 4; ++p) {
        float lo[8], hi[8];
#pragma unroll
        for (int c = 0; c < 8; ++c) {
            upk2(acc[p][c], lo[c], hi[c]);
            lo[c] += bb[c]; hi[c] += bb[c];
        }
        size_t r0 = (size_t)(m0 + ty * 8 + 2 * p) * UU + n0 + tx * 8;
        *reinterpret_cast<float4*>(C + r0)          = make_float4(lo[0], lo[1], lo[2], lo[3]);
        *reinterpret_cast<float4*>(C + r0 + 4)      = make_float4(lo[4], lo[5], lo[6], lo[7]);
        *reinterpret_cast<float4*>(C + r0 + UU)     = make_float4(hi[0], hi[1], hi[2], hi[3]);
        *reinterpret_cast<float4*>(C + r0 + UU + 4) = make_float4(hi[4], hi[5], hi[6], hi[7]);
    }
}

// ============================================================================
// Recurrence: 2 CTAs/SM. 8 warps = 8 k-chunks of 64; lane = col j x 16 rows.
// ============================================================================
__global__ void __launch_bounds__(NTR3, 2)
recur_kernel(const float* __restrict__ Wrec, int layer)
{
    extern __shared__ float smem[];
    float* sWT  = smem;                        // [32][SSTR] weight slice
    float* sSt  = smem + NCL3 * SSTR;          // [16][SSTR] staged H rows
    float* sRed = sSt;                         // ALIAS: [8 kc][16 r][RST3]

    const float* u    = g_U;
    float*       sout = (layer == 0) ? g_S0 : ((layer == 1) ? g_S1 : (float*)0);
    float* const hb0  = g_H[layer][0];
    float* const hb1  = g_H[layer][1];
    unsigned int* const barp = &g_bar[layer][blockIdx.x >> 4];

    const int tid  = threadIdx.x;
    const int lane = tid & 31;
    const int kc   = tid >> 5;                 // warp = k-chunk 0..7 (64 k each)
    const int grp  = blockIdx.x >> 4;          // batch group
    const int sl   = blockIdx.x & 15;          // col slice
    const int b0   = grp * BCR;
    const int col0 = sl * NCL3;
    const int kbase = kc * 64;

    // finalize ownership: thread -> rows {fi0, fi0+8}, col fj
    const int fi0 = tid >> 5;                  // 0..7
    const int fj  = lane;                      // 0..31

    // Load transposed weight slice: sWT[c][k] = Wrec[k][col0+c]
    for (int idx = tid; idx < NCL3 * UU; idx += NTR3) {
        int c = idx & 31, k = idx >> 5;
        sWT[c * SSTR + k] = Wrec[(size_t)k * UU + col0 + c];
    }
    __syncthreads();

    unsigned int tgt = 0;

    for (int t = 0; t < TT; ++t) {
        const int p = t & 1;
        const float* hsrc = p ? hb1 : hb0;
        float*       hdst = p ? hb0 : hb1;
        const size_t m0r = (size_t)(b0 + fi0) * TT + t;
        const size_t m1r = (size_t)(b0 + fi0 + 8) * TT + t;

        // prefetch u (constant during this launch) before the spin
        const float u0 = __ldg(u + m0r * UU + col0 + fj);
        const float u1 = __ldg(u + m1r * UU + col0 + fj);

        // ---- wait: peers' step t-1 stores must be visible ----
        if (t > 0) {
            if (tid == 0) {
                unsigned int v;
                do {
                    asm volatile("ld.acquire.gpu.u32 %0, [%1];"
                                 : "=r"(v) : "l"(barp));
                    if (v >= tgt) break;
                    __nanosleep(32);
                } while (true);
            }
            __syncthreads();
        }

        // ---- stage H[p] rows [16 x 512] from L2 ----
        for (int idx = tid; idx < BCR * 128; idx += NTR3) {
            int i = idx >> 7, c = idx & 127;
            float4 v = __ldcg(reinterpret_cast<const float4*>(
                                  hsrc + (size_t)(b0 + i) * UU) + c);
            reinterpret_cast<float4*>(sSt + i * SSTR)[c] = v;
        }
        __syncthreads();

        // ---- matmul: 16 rows x 1 col per lane over 64-k chunk ----
        unsigned long long acc[16];
#pragma unroll
        for (int r = 0; r < 16; ++r) acc[r] = 0ull;

        const ulonglong2* wp = reinterpret_cast<const ulonglong2*>(
            sWT + lane * SSTR + kbase);
        const float* abase = sSt + kbase;

#pragma unroll 4
        for (int c = 0; c < 16; ++c) {
            ulonglong2 w = wp[c];
#pragma unroll
            for (int r = 0; r < 16; ++r) {
                ulonglong2 a = *reinterpret_cast<const ulonglong2*>(
                    abase + r * SSTR + 4 * c);
                dfma2(acc[r], a.x, w.x);
                dfma2(acc[r], a.y, w.y);
            }
        }

        // read holds BEFORE sRed (alias) overwrites the stage
        const float hold0 = sSt[fi0 * SSTR + col0 + fj];
        const float hold1 = sSt[(fi0 + 8) * SSTR + col0 + fj];
        __syncthreads();

        // ---- partials: sRed[kc][r][lane] (stride-1 -> conflict-free) ----
        {
            float* base = sRed + (size_t)(kc * BCR) * RST3 + lane;
#pragma unroll
            for (int r = 0; r < 16; ++r)
                base[r * RST3] = dsum2(acc[r]);
        }
        __syncthreads();

        // ---- finalize: 2 outputs per thread (rows fi0, fi0+8) ----
        {
            float z0 = u0, z1 = u1;
            const float* rb0 = sRed + (size_t)fi0 * RST3 + fj;
            const float* rb1 = rb0 + 8 * RST3;
#pragma unroll
            for (int k2 = 0; k2 < 8; ++k2) {
                z0 += rb0[(size_t)k2 * (BCR * RST3)];
                z1 += rb1[(size_t)k2 * (BCR * RST3)];
            }
            float hn0 = hold0 * 0.1f + 0.9f * tanhf(z0);
            float hn1 = hold1 * 0.1f + 0.9f * tanhf(z1);
            size_t gh0 = (size_t)(b0 + fi0) * UU + col0 + fj;
            size_t gh1 = (size_t)(b0 + fi0 + 8) * UU + col0 + fj;
            hdst[gh0] = hn0;
            hdst[gh1] = hn1;
            if (sout) {
                sout[m0r * UU + col0 + fj] = hn0;
                sout[m1r * UU + col0 + fj] = hn1;
            }
            if (t == TT - 1) {
                g_R[(size_t)(b0 + fi0) * (3 * UU) + layer * UU + col0 + fj] = hn0;
                g_R[(size_t)(b0 + fi0 + 8) * (3 * UU) + layer * UU + col0 + fj] = hn1;
            }
        }

        // ---- arrive (release) ----
        if (t < TT - 1) {
            __syncthreads();
            tgt += NSL3;
            if (tid == 0) {
                asm volatile("fence.acq_rel.gpu;" ::: "memory");
                atomicAdd(barp, 1u);
            }
        }
    }
}

__global__ void init_kernel() {
    int idx = blockIdx.x * blockDim.x + threadIdx.x;
    if (idx < 3 * 2 * BB * UU) ((float*)g_H)[idx] = 0.0f;
    if (idx < 3 * NGRP) ((unsigned int*)g_bar)[idx] = 0u;
}

__global__ void readout_kernel(const float* __restrict__ Wout,
                               const float* __restrict__ bout,
                               float* __restrict__ out) {
    __shared__ float red[NCLS][NT];
    int b = blockIdx.x, tid = threadIdx.x;
    float part[NCLS];
#pragma unroll
    for (int c = 0; c < NCLS; ++c) part[c] = 0.0f;
    for (int k = tid; k < 3 * UU; k += NT) {
        float r = g_R[(size_t)b * 3 * UU + k];
#pragma unroll
        for (int c = 0; c < NCLS; ++c) part[c] += r * Wout[k * NCLS + c];
    }
#pragma unroll
    for (int c = 0; c < NCLS; ++c) red[c][tid] = part[c];
    __syncthreads();
    if (tid < NCLS) {
        float s = 0.0f;
        for (int i = 0; i < NT; ++i) s += red[tid][i];
        out[b * NCLS + tid] = s + bout[tid];
    }
}

extern "C" void kernel_launch(void* const* d_in, const int* in_sizes, int n_in,
                              void* d_out, int out_size) {
    (void)in_sizes; (void)n_in; (void)out_size;
    const float* x    = (const float*)d_in[0];
    const float* Win0 = (const float*)d_in[1];
    const float* W0   = (const float*)d_in[2];
    const float* b0   = (const float*)d_in[3];
    const float* Win1 = (const float*)d_in[4];
    const float* W1   = (const float*)d_in[5];
    const float* b1   = (const float*)d_in[6];
    const float* Win2 = (const float*)d_in[7];
    const float* W2   = (const float*)d_in[8];
    const float* b2   = (const float*)d_in[9];
    const float* Wout = (const float*)d_in[10];
    const float* bout = (const float*)d_in[11];
    float* out = (float*)d_out;

    // recur smem: 32x516 + 16x516 = 24,768 floats = 99,072 B  (2 CTAs/SM)
    const int smem = (NCL3 * SSTR + BCR * SSTR) * (int)sizeof(float);
    static int attr_done = 0;
    if (!attr_done) {
        cudaFuncSetAttribute(recur_kernel,
                             cudaFuncAttributeMaxDynamicSharedMemorySize, smem);
        attr_done = 1;
    }

    const dim3 ggrid(4, (BB * TT) / 128);
    const dim3 hgrid(2, (BB * TT) / 128);

    init_kernel<<<3072, NT>>>();                             // launch 1
    drive_gemm<<<hgrid, NT>>>(x, Win0, b0, 64, 0, 0);        // launch 2
    drive_gemm<<<hgrid, NT>>>(x, Win0, b0, 64, 0, 256);      // launch 3
    recur_kernel<<<NGRP * NSL3, NTR3, smem>>>(W0, 0);        // launch 4 (ncu aim)
    drive_gemm<<<ggrid, NT>>>(x, Win1, b1, 512, 1, 0);
    recur_kernel<<<NGRP * NSL3, NTR3, smem>>>(W1, 1);
    drive_gemm<<<ggrid, NT>>>(x, Win2, b2, 512, 2, 0);
    recur_kernel<<<NGRP * NSL3, NTR3, smem>>>(W2, 2);
    readout_kernel<<<BB, NT>>>(Wout, bout, out);
}

// round 14
// speedup vs baseline: 1.2035x; 1.0974x over previous
#include <cuda_runtime.h>

// ---------------------------------------------------------------------------
// DeepESN on B200 (sm_100a), round 14 = R11 base + own-chunk pre-compute.
//   recurrence: 128 CTAs = 16 batch-groups (16 rows) x 8 col-slices (64 cols)
//     512 threads = 16 warps = 2 rowgroups x 8 k-chunks; acc 8x2 f32x2.
//     NEW: the CTA's own 64 h-cols double as 64 k-values and are carried in
//     SMEM -> each warp computes its 8-k slice of the own chunk BEFORE the
//     cross-CTA spin (hides barrier slack); post-barrier matmul covers the
//     448 foreign k via a circular remap (56 k = 14 quads per warp-pair).
//     Stage buffer pre-zeroed -> uniform foreign-only staging every step.
// ---------------------------------------------------------------------------

#define BB   256
#define TT   512
#define UU   512
#define NCLS 10

#define NGRP 16
#define BCR  16
#define NSLC 8
#define NCOL 64
#define SSTR 516
#define RSTR 66
#define NTR  512
#define NT   256

#define AST2 132
#define BST2 132

__device__ float        g_S0[(size_t)BB * TT * UU];
__device__ float        g_S1[(size_t)BB * TT * UU];
__device__ float        g_U [(size_t)BB * TT * UU];
__device__ float        g_H[3][2][BB * UU];
__device__ float        g_R[BB * 3 * UU];
__device__ unsigned int g_bar[3][NGRP];

__device__ __forceinline__ void dfma2(unsigned long long& d,
                                      unsigned long long a,
                                      unsigned long long b) {
    asm("fma.rn.f32x2 %0, %1, %2, %0;" : "+l"(d) : "l"(a), "l"(b));
}
__device__ __forceinline__ float dsum2(unsigned long long v) {
    float lo, hi;
    asm("mov.b64 {%0, %1}, %2;" : "=f"(lo), "=f"(hi) : "l"(v));
    return lo + hi;
}
__device__ __forceinline__ unsigned long long pk2(float x) {
    unsigned long long r;
    asm("mov.b64 %0, {%1, %1};" : "=l"(r) : "f"(x));
    return r;
}
__device__ __forceinline__ void upk2(unsigned long long v, float& lo, float& hi) {
    asm("mov.b64 {%0, %1}, %2;" : "=f"(lo), "=f"(hi) : "l"(v));
}

// ============================================================================
// Drive GEMM (unchanged): g_U[M,512] = A[M,K] @ W[K,512] + bias.
// ============================================================================
__global__ void __launch_bounds__(NT)
drive_gemm(const float* __restrict__ x, const float* __restrict__ W,
           const float* __restrict__ bias, int K, int layer, int n_base)
{
    __shared__ float As[8 * AST2];
    __shared__ float Bs[8 * BST2];

    const float* A = (layer == 0) ? x : ((layer == 1) ? g_S0 : g_S1);
    float*       C = g_U;

    const int tid = threadIdx.x;
    const int tx  = tid & 15;
    const int ty  = tid >> 4;
    const int m0  = blockIdx.y * 128;
    const int n0  = n_base + blockIdx.x * 128;

    const int arow  = tid >> 1;
    const int ahalf = tid & 1;
    const int bk    = tid >> 5;
    const int bc4   = tid & 31;

    unsigned long long acc[4][8];
#pragma unroll
    for (int p = 0; p < 4; ++p)
#pragma unroll
        for (int c = 0; c < 8; ++c) acc[p][c] = 0ull;

    for (int kt = 0; kt < K; kt += 8) {
        {
            float4 va = __ldg(reinterpret_cast<const float4*>(
                                  A + (size_t)(m0 + arow) * K + kt + ahalf * 4));
            As[(ahalf * 4 + 0) * AST2 + arow] = va.x;
            As[(ahalf * 4 + 1) * AST2 + arow] = va.y;
            As[(ahalf * 4 + 2) * AST2 + arow] = va.z;
            As[(ahalf * 4 + 3) * AST2 + arow] = va.w;
            float4 vb = __ldg(reinterpret_cast<const float4*>(
                                  W + (size_t)(kt + bk) * UU + n0 + bc4 * 4));
            *reinterpret_cast<float4*>(Bs + bk * BST2 + bc4 * 4) = vb;
        }
        __syncthreads();

#pragma unroll
        for (int k = 0; k < 8; ++k) {
            unsigned long long a[4];
#pragma unroll
            for (int p = 0; p < 4; ++p)
                a[p] = *reinterpret_cast<const unsigned long long*>(
                           As + k * AST2 + ty * 8 + 2 * p);
            float4 b0 = *reinterpret_cast<const float4*>(Bs + k * BST2 + tx * 8);
            float4 b1 = *reinterpret_cast<const float4*>(Bs + k * BST2 + tx * 8 + 4);
            unsigned long long bb[8] = {pk2(b0.x), pk2(b0.y), pk2(b0.z), pk2(b0.w),
                                        pk2(b1.x), pk2(b1.y), pk2(b1.z), pk2(b1.w)};
#pragma unroll
            for (int p = 0; p < 4; ++p)
#pragma unroll
                for (int c = 0; c < 8; ++c)
                    dfma2(acc[p][c], a[p], bb[c]);
        }
        __syncthreads();
    }

    float4 bv0 = __ldg(reinterpret_cast<const float4*>(bias + n0 + tx * 8));
    float4 bv1 = __ldg(reinterpret_cast<const float4*>(bias + n0 + tx * 8 + 4));
    const float bb[8] = {bv0.x, bv0.y, bv0.z, bv0.w, bv1.x, bv1.y, bv1.z, bv1.w};
#pragma unroll
    for (int p = 0; p < 4; ++p) {
        float lo[8], hi[8];
#pragma unroll
        for (int c = 0; c < 8; ++c) {
            upk2(acc[p][c], lo[c], hi[c]);
            lo[c] += bb[c]; hi[c] += bb[c];
        }
        size_t r0 = (size_t)(m0 + ty * 8 + 2 * p) * UU + n0 + tx * 8;
        *reinterpret_cast<float4*>(C + r0)          = make_float4(lo[0], lo[1], lo[2], lo[3]);
        *reinterpret_cast<float4*>(C + r0 + 4)      = make_float4(lo[4], lo[5], lo[6], lo[7]);
        *reinterpret_cast<float4*>(C + r0 + UU)     = make_float4(hi[0], hi[1], hi[2], hi[3]);
        *reinterpret_cast<float4*>(C + r0 + UU + 4) = make_float4(hi[4], hi[5], hi[6], hi[7]);
    }
}

// ============================================================================
// Recurrence with own-chunk pre-compute + circular foreign k-remap.
// ============================================================================
__global__ void __launch_bounds__(NTR, 1)
recur_kernel(const float* __restrict__ Wrec, int layer)
{
    extern __shared__ float smem[];
    float* sWT  = smem;                       // [64][SSTR]
    float* sSt  = smem + NCOL * SSTR;         // [16][SSTR]
    float* sRed = sSt + BCR * SSTR;           // [128][RSTR] de-aliased

    const float* u    = g_U;
    float*       sout = (layer == 0) ? g_S0 : ((layer == 1) ? g_S1 : (float*)0);
    float* const hb0  = g_H[layer][0];
    float* const hb1  = g_H[layer][1];
    unsigned int* const barp = &g_bar[layer][blockIdx.x >> 3];

    const int tid  = threadIdx.x;
    const int lane = tid & 31;
    const int wid  = tid >> 5;
    const int rg   = wid & 1;                 // rowgroup
    const int kc   = wid >> 1;                // chunk id 0..7
    const int grp  = blockIdx.x >> 3;
    const int sl   = blockIdx.x & 7;
    const int b0   = grp * BCR;
    const int col0 = sl * NCOL;
    const int own0 = sl * 16;                 // own slice, float4 units
    (void)grp;

    const int fi = tid >> 5;                  // finalize row 0..15
    const int fj = lane;                      // finalize cols (fj, fj+32)

    // weight slice: sWT[c][k] = Wrec[k][col0+c]
    for (int idx = tid; idx < NCOL * UU; idx += NTR) {
        int c = idx & 63, k = idx >> 6;
        sWT[c * SSTR + k] = Wrec[(size_t)k * UU + col0 + c];
    }
    // zero the stage (h(0) = 0; makes all steps uniform incl. t=0)
    for (int idx = tid; idx < BCR * 512; idx += NTR) {
        int i = idx >> 9, c = idx & 511;
        sSt[i * SSTR + c] = 0.0f;
    }
    __syncthreads();

    for (int t = 0; t < TT; ++t) {
        const int p = t & 1;
        const float* hsrc = p ? hb1 : hb0;
        float*       hdst = p ? hb0 : hb1;
        const size_t m = (size_t)(b0 + fi) * TT + t;

        // ---- phase 1 (pre-barrier): own 8-k slice from carried own cols ----
        unsigned long long acc[8][2];
#pragma unroll
        for (int r = 0; r < 8; ++r) { acc[r][0] = 0ull; acc[r][1] = 0ull; }
        {
            const int kown = col0 + kc * 8;
            const ulonglong2* w0p = reinterpret_cast<const ulonglong2*>(
                sWT + lane * SSTR + kown);
            const ulonglong2* w1p = reinterpret_cast<const ulonglong2*>(
                sWT + (lane + 32) * SSTR + kown);
            const float* arow = sSt + rg * 8 * SSTR + kown;
#pragma unroll
            for (int q = 0; q < 2; ++q) {
                ulonglong2 w0 = w0p[q];
                ulonglong2 w1 = w1p[q];
#pragma unroll
                for (int r = 0; r < 8; ++r) {
                    ulonglong2 a = *reinterpret_cast<const ulonglong2*>(
                        arow + r * SSTR + 4 * q);
                    dfma2(acc[r][0], a.x, w0.x);
                    dfma2(acc[r][0], a.y, w0.y);
                    dfma2(acc[r][1], a.x, w1.x);
                    dfma2(acc[r][1], a.y, w1.y);
                }
            }
        }

        // u prefetch (constant during launch)
        const float u0 = __ldg(u + m * UU + col0 + fj);
        const float u1 = __ldg(u + m * UU + col0 + fj + 32);

        // ---- wait: peers' step t-1 stores visible ----  [S1]
        if (t > 0) {
            if (tid == 0) {
                const unsigned int tgt = (unsigned int)t * NSLC;
                unsigned int v;
                do {
                    asm volatile("ld.acquire.gpu.u32 %0, [%1];"
                                 : "=r"(v) : "l"(barp));
                    if (v >= tgt) break;
                    __nanosleep(32);
                } while (true);
            }
            __syncthreads();
        }

        // ---- stage foreign 448 cols (own 64 carried in sSt) ----
        for (int idx = tid; idx < BCR * 112; idx += NTR) {
            int i = idx / 112, c = idx - i * 112;
            int c4 = (c < own0) ? c : c + 16;
            float4 v = __ldcg(reinterpret_cast<const float4*>(
                                  hsrc + (size_t)(b0 + i) * UU) + c4);
            reinterpret_cast<float4*>(sSt + i * SSTR)[c4] = v;
        }
        __syncthreads();                       // [S2]

        // ---- phase 2: foreign 56-k chunk (circular remap) ----
        {
            const int fbase = col0 + 64 + kc * 56;
            const float* wl0 = sWT + lane * SSTR;
            const float* wl1 = sWT + (lane + 32) * SSTR;
            const float* ar0 = sSt + rg * 8 * SSTR;
#pragma unroll 2
            for (int q = 0; q < 14; ++q) {
                const int kq = (fbase + 4 * q) & 511;
                ulonglong2 w0 = *reinterpret_cast<const ulonglong2*>(wl0 + kq);
                ulonglong2 w1 = *reinterpret_cast<const ulonglong2*>(wl1 + kq);
                const float* arow = ar0 + kq;
#pragma unroll
                for (int r = 0; r < 8; ++r) {
                    ulonglong2 a = *reinterpret_cast<const ulonglong2*>(
                        arow + r * SSTR);
                    dfma2(acc[r][0], a.x, w0.x);
                    dfma2(acc[r][0], a.y, w0.y);
                    dfma2(acc[r][1], a.x, w1.x);
                    dfma2(acc[r][1], a.y, w1.y);
                }
            }
        }

        // ---- partials ----
        {
            float* base = sRed + (size_t)(kc * 16 + rg * 8) * RSTR + lane * 2;
#pragma unroll
            for (int r = 0; r < 8; ++r) {
                float2 v;
                v.x = dsum2(acc[r][0]);
                v.y = dsum2(acc[r][1]);
                *reinterpret_cast<float2*>(base + r * RSTR) = v;
            }
        }
        __syncthreads();                       // [S3]

        // ---- finalize: 2 outputs per thread ----
        {
            float z0 = u0, z1 = u1;
            const float* rb = sRed + (size_t)fi * RSTR + fj * 2;
#pragma unroll
            for (int k2 = 0; k2 < 8; ++k2) {
                float2 pv = *reinterpret_cast<const float2*>(
                    rb + (size_t)k2 * (16 * RSTR));
                z0 += pv.x; z1 += pv.y;
            }
            const float hold0 = sSt[fi * SSTR + col0 + fj];
            const float hold1 = sSt[fi * SSTR + col0 + fj + 32];
            float hn0 = hold0 * 0.1f + 0.9f * tanhf(z0);
            float hn1 = hold1 * 0.1f + 0.9f * tanhf(z1);
            size_t gh = (size_t)(b0 + fi) * UU + col0 + fj;
            hdst[gh]      = hn0;
            hdst[gh + 32] = hn1;
            sSt[fi * SSTR + col0 + fj]      = hn0;   // own-slice carry
            sSt[fi * SSTR + col0 + fj + 32] = hn1;
            if (sout) {
                sout[m * UU + col0 + fj]      = hn0;
                sout[m * UU + col0 + fj + 32] = hn1;
            }
            if (t == TT - 1) {
                size_t gr = (size_t)(b0 + fi) * (3 * UU) + layer * UU + col0 + fj;
                g_R[gr]      = hn0;
                g_R[gr + 32] = hn1;
            }
        }

        // ---- arrive ----                    [S4]
        if (t < TT - 1) {
            __syncthreads();
            if (tid == 0) {
                asm volatile("fence.acq_rel.gpu;" ::: "memory");
                atomicAdd(barp, 1u);
            }
        }
    }
}

__global__ void init_kernel() {
    int idx = blockIdx.x * blockDim.x + threadIdx.x;
    if (idx < 3 * 2 * BB * UU) ((float*)g_H)[idx] = 0.0f;
    if (idx < 3 * NGRP) ((unsigned int*)g_bar)[idx] = 0u;
}

__global__ void readout_kernel(const float* __restrict__ Wout,
                               const float* __restrict__ bout,
                               float* __restrict__ out) {
    __shared__ float red[NCLS][NT];
    int b = blockIdx.x, tid = threadIdx.x;
    float part[NCLS];
#pragma unroll
    for (int c = 0; c < NCLS; ++c) part[c] = 0.0f;
    for (int k = tid; k < 3 * UU; k += NT) {
        float r = g_R[(size_t)b * 3 * UU + k];
#pragma unroll
        for (int c = 0; c < NCLS; ++c) part[c] += r * Wout[k * NCLS + c];
    }
#pragma unroll
    for (int c = 0; c < NCLS; ++c) red[c][tid] = part[c];
    __syncthreads();
    if (tid < NCLS) {
        float s = 0.0f;
        for (int i = 0; i < NT; ++i) s += red[tid][i];
        out[b * NCLS + tid] = s + bout[tid];
    }
}

extern "C" void kernel_launch(void* const* d_in, const int* in_sizes, int n_in,
                              void* d_out, int out_size) {
    (void)in_sizes; (void)n_in; (void)out_size;
    const float* x    = (const float*)d_in[0];
    const float* Win0 = (const float*)d_in[1];
    const float* W0   = (const float*)d_in[2];
    const float* b0   = (const float*)d_in[3];
    const float* Win1 = (const float*)d_in[4];
    const float* W1   = (const float*)d_in[5];
    const float* b1   = (const float*)d_in[6];
    const float* Win2 = (const float*)d_in[7];
    const float* W2   = (const float*)d_in[8];
    const float* b2   = (const float*)d_in[9];
    const float* Wout = (const float*)d_in[10];
    const float* bout = (const float*)d_in[11];
    float* out = (float*)d_out;

    // smem: 64x516 + 16x516 + 128x66 = 198,912 B (1 CTA/SM)
    const int smem = (NCOL * SSTR + BCR * SSTR + 128 * RSTR) * (int)sizeof(float);
    static int attr_done = 0;
    if (!attr_done) {
        cudaFuncSetAttribute(recur_kernel,
                             cudaFuncAttributeMaxDynamicSharedMemorySize, smem);
        attr_done = 1;
    }

    const dim3 ggrid(4, (BB * TT) / 128);
    const dim3 hgrid(2, (BB * TT) / 128);

    init_kernel<<<3072, NT>>>();                             // launch 1
    drive_gemm<<<hgrid, NT>>>(x, Win0, b0, 64, 0, 0);        // launch 2
    drive_gemm<<<hgrid, NT>>>(x, Win0, b0, 64, 0, 256);      // launch 3
    recur_kernel<<<NGRP * NSLC, NTR, smem>>>(W0, 0);         // launch 4 (ncu aim)
    drive_gemm<<<ggrid, NT>>>(x, Win1, b1, 512, 1, 0);
    recur_kernel<<<NGRP * NSLC, NTR, smem>>>(W1, 1);
    drive_gemm<<<ggrid, NT>>>(x, Win2, b2, 512, 2, 0);
    recur_kernel<<<NGRP * NSLC, NTR, smem>>>(W2, 2);
    readout_kernel<<<BB, NT>>>(Wout, bout, out);
}

// round 15
// speedup vs baseline: 1.2641x; 1.0504x over previous
#include <cuda_runtime.h>

// ---------------------------------------------------------------------------
// DeepESN on B200 (sm_100a), round 15 = R14 + warp-autonomous wait/stage +
// tanh.approx.
//   recurrence: 128 CTAs = 16 batch-groups (16 rows) x 8 col-slices (64 cols)
//     512 threads = 16 warps = 2 rowgroups x 8 k-chunks; acc 8x2 f32x2.
//     Own 64 h-cols carried in SMEM; own-chunk FMA before the wait.
//     NEW: each warp polls the group counter itself (acquire) and stages ONLY
//     its own 8 rows x 56 foreign cols, then __syncwarp -> the two CTA-wide
//     barriers around staging are gone and L2 latency is warp-overlapped.
//     NEW: tanh.approx.f32 (MUFU) in the state update.
//     Per-step CTA syncs: S3 (before reduce) and S4 (before arrive) only.
// ---------------------------------------------------------------------------

#define BB   256
#define TT   512
#define UU   512
#define NCLS 10

#define NGRP 16
#define BCR  16
#define NSLC 8
#define NCOL 64
#define SSTR 516
#define RSTR 66
#define NTR  512
#define NT   256

#define AST2 132
#define BST2 132

__device__ float        g_S0[(size_t)BB * TT * UU];
__device__ float        g_S1[(size_t)BB * TT * UU];
__device__ float        g_U [(size_t)BB * TT * UU];
__device__ float        g_H[3][2][BB * UU];
__device__ float        g_R[BB * 3 * UU];
__device__ unsigned int g_bar[3][NGRP];

__device__ __forceinline__ void dfma2(unsigned long long& d,
                                      unsigned long long a,
                                      unsigned long long b) {
    asm("fma.rn.f32x2 %0, %1, %2, %0;" : "+l"(d) : "l"(a), "l"(b));
}
__device__ __forceinline__ float dsum2(unsigned long long v) {
    float lo, hi;
    asm("mov.b64 {%0, %1}, %2;" : "=f"(lo), "=f"(hi) : "l"(v));
    return lo + hi;
}
__device__ __forceinline__ unsigned long long pk2(float x) {
    unsigned long long r;
    asm("mov.b64 %0, {%1, %1};" : "=l"(r) : "f"(x));
    return r;
}
__device__ __forceinline__ void upk2(unsigned long long v, float& lo, float& hi) {
    asm("mov.b64 {%0, %1}, %2;" : "=f"(lo), "=f"(hi) : "l"(v));
}
__device__ __forceinline__ float tanh_fast(float x) {
    float r;
    asm("tanh.approx.f32 %0, %1;" : "=f"(r) : "f"(x));
    return r;
}

// ============================================================================
// Drive GEMM (unchanged): g_U[M,512] = A[M,K] @ W[K,512] + bias.
// ============================================================================
__global__ void __launch_bounds__(NT)
drive_gemm(const float* __restrict__ x, const float* __restrict__ W,
           const float* __restrict__ bias, int K, int layer, int n_base)
{
    __shared__ float As[8 * AST2];
    __shared__ float Bs[8 * BST2];

    const float* A = (layer == 0) ? x : ((layer == 1) ? g_S0 : g_S1);
    float*       C = g_U;

    const int tid = threadIdx.x;
    const int tx  = tid & 15;
    const int ty  = tid >> 4;
    const int m0  = blockIdx.y * 128;
    const int n0  = n_base + blockIdx.x * 128;

    const int arow  = tid >> 1;
    const int ahalf = tid & 1;
    const int bk    = tid >> 5;
    const int bc4   = tid & 31;

    unsigned long long acc[4][8];
#pragma unroll
    for (int p = 0; p < 4; ++p)
#pragma unroll
        for (int c = 0; c < 8; ++c) acc[p][c] = 0ull;

    for (int kt = 0; kt < K; kt += 8) {
        {
            float4 va = __ldg(reinterpret_cast<const float4*>(
                                  A + (size_t)(m0 + arow) * K + kt + ahalf * 4));
            As[(ahalf * 4 + 0) * AST2 + arow] = va.x;
            As[(ahalf * 4 + 1) * AST2 + arow] = va.y;
            As[(ahalf * 4 + 2) * AST2 + arow] = va.z;
            As[(ahalf * 4 + 3) * AST2 + arow] = va.w;
            float4 vb = __ldg(reinterpret_cast<const float4*>(
                                  W + (size_t)(kt + bk) * UU + n0 + bc4 * 4));
            *reinterpret_cast<float4*>(Bs + bk * BST2 + bc4 * 4) = vb;
        }
        __syncthreads();

#pragma unroll
        for (int k = 0; k < 8; ++k) {
            unsigned long long a[4];
#pragma unroll
            for (int p = 0; p < 4; ++p)
                a[p] = *reinterpret_cast<const unsigned long long*>(
                           As + k * AST2 + ty * 8 + 2 * p);
            float4 b0 = *reinterpret_cast<const float4*>(Bs + k * BST2 + tx * 8);
            float4 b1 = *reinterpret_cast<const float4*>(Bs + k * BST2 + tx * 8 + 4);
            unsigned long long bb[8] = {pk2(b0.x), pk2(b0.y), pk2(b0.z), pk2(b0.w),
                                        pk2(b1.x), pk2(b1.y), pk2(b1.z), pk2(b1.w)};
#pragma unroll
            for (int p = 0; p < 4; ++p)
#pragma unroll
                for (int c = 0; c < 8; ++c)
                    dfma2(acc[p][c], a[p], bb[c]);
        }
        __syncthreads();
    }

    float4 bv0 = __ldg(reinterpret_cast<const float4*>(bias + n0 + tx * 8));
    float4 bv1 = __ldg(reinterpret_cast<const float4*>(bias + n0 + tx * 8 + 4));
    const float bb[8] = {bv0.x, bv0.y, bv0.z, bv0.w, bv1.x, bv1.y, bv1.z, bv1.w};
#pragma unroll
    for (int p = 0; p < 4; ++p) {
        float lo[8], hi[8];
#pragma unroll
        for (int c = 0; c < 8; ++c) {
            upk2(acc[p][c], lo[c], hi[c]);
            lo[c] += bb[c]; hi[c] += bb[c];
        }
        size_t r0 = (size_t)(m0 + ty * 8 + 2 * p) * UU + n0 + tx * 8;
        *reinterpret_cast<float4*>(C + r0)          = make_float4(lo[0], lo[1], lo[2], lo[3]);
        *reinterpret_cast<float4*>(C + r0 + 4)      = make_float4(lo[4], lo[5], lo[6], lo[7]);
        *reinterpret_cast<float4*>(C + r0 + UU)     = make_float4(hi[0], hi[1], hi[2], hi[3]);
        *reinterpret_cast<float4*>(C + r0 + UU + 4) = make_float4(hi[4], hi[5], hi[6], hi[7]);
    }
}

// ============================================================================
// Recurrence: warp-autonomous wait + per-warp staging.
// ============================================================================
__global__ void __launch_bounds__(NTR, 1)
recur_kernel(const float* __restrict__ Wrec, int layer)
{
    extern __shared__ float smem[];
    float* sWT  = smem;                       // [64][SSTR]
    float* sSt  = smem + NCOL * SSTR;         // [16][SSTR]
    float* sRed = sSt + BCR * SSTR;           // [128][RSTR]

    const float* u    = g_U;
    float*       sout = (layer == 0) ? g_S0 : ((layer == 1) ? g_S1 : (float*)0);
    float* const hb0  = g_H[layer][0];
    float* const hb1  = g_H[layer][1];
    unsigned int* const barp = &g_bar[layer][blockIdx.x >> 3];

    const int tid  = threadIdx.x;
    const int lane = tid & 31;
    const int wid  = tid >> 5;
    const int rg   = wid & 1;                 // rowgroup
    const int kc   = wid >> 1;                // chunk id 0..7
    const int grp  = blockIdx.x >> 3;
    const int sl   = blockIdx.x & 7;
    const int b0   = grp * BCR;
    const int col0 = sl * NCOL;
    (void)grp;

    const int fi = tid >> 5;                  // finalize row 0..15
    const int fj = lane;                      // finalize cols (fj, fj+32)

    // weight slice: sWT[c][k] = Wrec[k][col0+c]
    for (int idx = tid; idx < NCOL * UU; idx += NTR) {
        int c = idx & 63, k = idx >> 6;
        sWT[c * SSTR + k] = Wrec[(size_t)k * UU + col0 + c];
    }
    // zero the stage (h(0) = 0; all steps uniform incl. t=0)
    for (int idx = tid; idx < BCR * 512; idx += NTR) {
        int i = idx >> 9, c = idx & 511;
        sSt[i * SSTR + c] = 0.0f;
    }
    __syncthreads();

    for (int t = 0; t < TT; ++t) {
        const int p = t & 1;
        const float* hsrc = p ? hb1 : hb0;
        float*       hdst = p ? hb0 : hb1;
        const size_t m = (size_t)(b0 + fi) * TT + t;

        // ---- phase 1 (pre-wait): own 8-k slice from carried own cols ----
        unsigned long long acc[8][2];
#pragma unroll
        for (int r = 0; r < 8; ++r) { acc[r][0] = 0ull; acc[r][1] = 0ull; }
        {
            const int kown = col0 + kc * 8;
            const ulonglong2* w0p = reinterpret_cast<const ulonglong2*>(
                sWT + lane * SSTR + kown);
            const ulonglong2* w1p = reinterpret_cast<const ulonglong2*>(
                sWT + (lane + 32) * SSTR + kown);
            const float* arow = sSt + rg * 8 * SSTR + kown;
#pragma unroll
            for (int q = 0; q < 2; ++q) {
                ulonglong2 w0 = w0p[q];
                ulonglong2 w1 = w1p[q];
#pragma unroll
                for (int r = 0; r < 8; ++r) {
                    ulonglong2 a = *reinterpret_cast<const ulonglong2*>(
                        arow + r * SSTR + 4 * q);
                    dfma2(acc[r][0], a.x, w0.x);
                    dfma2(acc[r][0], a.y, w0.y);
                    dfma2(acc[r][1], a.x, w1.x);
                    dfma2(acc[r][1], a.y, w1.y);
                }
            }
        }

        // u prefetch (constant during launch)
        const float u0 = __ldg(u + m * UU + col0 + fj);
        const float u1 = __ldg(u + m * UU + col0 + fj + 32);

        // ---- per-warp wait + per-warp stage of own 8 rows x 56 cols ----
        if (t > 0) {
            const unsigned int tgt = (unsigned int)t * NSLC;
            unsigned int v;
            do {
                asm volatile("ld.acquire.gpu.u32 %0, [%1];"
                             : "=r"(v) : "l"(barp));
                if (v >= tgt) break;
                __nanosleep(16);
            } while (true);

            const int fbase = col0 + 64 + kc * 56;
            const int grow  = b0 + rg * 8;
            for (int idx = lane; idx < 112; idx += 32) {
                int i = idx / 14, q = idx - i * 14;
                int c = (fbase + 4 * q) & 511;
                float4 v4 = __ldcg(reinterpret_cast<const float4*>(
                                       hsrc + (size_t)(grow + i) * UU + c));
                *reinterpret_cast<float4*>(sSt + (rg * 8 + i) * SSTR + c) = v4;
            }
            __syncwarp();
        }

        // ---- phase 2: foreign 56-k chunk (circular remap, own staging) ----
        {
            const int fbase = col0 + 64 + kc * 56;
            const float* wl0 = sWT + lane * SSTR;
            const float* wl1 = sWT + (lane + 32) * SSTR;
            const float* ar0 = sSt + rg * 8 * SSTR;
#pragma unroll 2
            for (int q = 0; q < 14; ++q) {
                const int kq = (fbase + 4 * q) & 511;
                ulonglong2 w0 = *reinterpret_cast<const ulonglong2*>(wl0 + kq);
                ulonglong2 w1 = *reinterpret_cast<const ulonglong2*>(wl1 + kq);
                const float* arow = ar0 + kq;
#pragma unroll
                for (int r = 0; r < 8; ++r) {
                    ulonglong2 a = *reinterpret_cast<const ulonglong2*>(
                        arow + r * SSTR);
                    dfma2(acc[r][0], a.x, w0.x);
                    dfma2(acc[r][0], a.y, w0.y);
                    dfma2(acc[r][1], a.x, w1.x);
                    dfma2(acc[r][1], a.y, w1.y);
                }
            }
        }

        // ---- partials ----
        {
            float* base = sRed + (size_t)(kc * 16 + rg * 8) * RSTR + lane * 2;
#pragma unroll
            for (int r = 0; r < 8; ++r) {
                float2 v;
                v.x = dsum2(acc[r][0]);
                v.y = dsum2(acc[r][1]);
                *reinterpret_cast<float2*>(base + r * RSTR) = v;
            }
        }
        __syncthreads();                       // [S3]

        // ---- finalize: 2 outputs per thread ----
        {
            float z0 = u0, z1 = u1;
            const float* rb = sRed + (size_t)fi * RSTR + fj * 2;
#pragma unroll
            for (int k2 = 0; k2 < 8; ++k2) {
                float2 pv = *reinterpret_cast<const float2*>(
                    rb + (size_t)k2 * (16 * RSTR));
                z0 += pv.x; z1 += pv.y;
            }
            const float hold0 = sSt[fi * SSTR + col0 + fj];
            const float hold1 = sSt[fi * SSTR + col0 + fj + 32];
            float hn0 = hold0 * 0.1f + 0.9f * tanh_fast(z0);
            float hn1 = hold1 * 0.1f + 0.9f * tanh_fast(z1);
            size_t gh = (size_t)(b0 + fi) * UU + col0 + fj;
            hdst[gh]      = hn0;
            hdst[gh + 32] = hn1;
            sSt[fi * SSTR + col0 + fj]      = hn0;   // own-slice carry
            sSt[fi * SSTR + col0 + fj + 32] = hn1;
            if (sout) {
                sout[m * UU + col0 + fj]      = hn0;
                sout[m * UU + col0 + fj + 32] = hn1;
            }
            if (t == TT - 1) {
                size_t gr = (size_t)(b0 + fi) * (3 * UU) + layer * UU + col0 + fj;
                g_R[gr]      = hn0;
                g_R[gr + 32] = hn1;
            }
        }

        // ---- arrive ----                    [S4]
        if (t < TT - 1) {
            __syncthreads();
            if (tid == 0) {
                asm volatile("fence.acq_rel.gpu;" ::: "memory");
                atomicAdd(barp, 1u);
            }
        }
    }
}

__global__ void init_kernel() {
    int idx = blockIdx.x * blockDim.x + threadIdx.x;
    if (idx < 3 * 2 * BB * UU) ((float*)g_H)[idx] = 0.0f;
    if (idx < 3 * NGRP) ((unsigned int*)g_bar)[idx] = 0u;
}

__global__ void readout_kernel(const float* __restrict__ Wout,
                               const float* __restrict__ bout,
                               float* __restrict__ out) {
    __shared__ float red[NCLS][NT];
    int b = blockIdx.x, tid = threadIdx.x;
    float part[NCLS];
#pragma unroll
    for (int c = 0; c < NCLS; ++c) part[c] = 0.0f;
    for (int k = tid; k < 3 * UU; k += NT) {
        float r = g_R[(size_t)b * 3 * UU + k];
#pragma unroll
        for (int c = 0; c < NCLS; ++c) part[c] += r * Wout[k * NCLS + c];
    }
#pragma unroll
    for (int c = 0; c < NCLS; ++c) red[c][tid] = part[c];
    __syncthreads();
    if (tid < NCLS) {
        float s = 0.0f;
        for (int i = 0; i < NT; ++i) s += red[tid][i];
        out[b * NCLS + tid] = s + bout[tid];
    }
}

extern "C" void kernel_launch(void* const* d_in, const int* in_sizes, int n_in,
                              void* d_out, int out_size) {
    (void)in_sizes; (void)n_in; (void)out_size;
    const float* x    = (const float*)d_in[0];
    const float* Win0 = (const float*)d_in[1];
    const float* W0   = (const float*)d_in[2];
    const float* b0   = (const float*)d_in[3];
    const float* Win1 = (const float*)d_in[4];
    const float* W1   = (const float*)d_in[5];
    const float* b1   = (const float*)d_in[6];
    const float* Win2 = (const float*)d_in[7];
    const float* W2   = (const float*)d_in[8];
    const float* b2   = (const float*)d_in[9];
    const float* Wout = (const float*)d_in[10];
    const float* bout = (const float*)d_in[11];
    float* out = (float*)d_out;

    // smem: 64x516 + 16x516 + 128x66 = 198,912 B (1 CTA/SM)
    const int smem = (NCOL * SSTR + BCR * SSTR + 128 * RSTR) * (int)sizeof(float);
    static int attr_done = 0;
    if (!attr_done) {
        cudaFuncSetAttribute(recur_kernel,
                             cudaFuncAttributeMaxDynamicSharedMemorySize, smem);
        attr_done = 1;
    }

    const dim3 ggrid(4, (BB * TT) / 128);
    const dim3 hgrid(2, (BB * TT) / 128);

    init_kernel<<<3072, NT>>>();                             // launch 1
    drive_gemm<<<hgrid, NT>>>(x, Win0, b0, 64, 0, 0);        // launch 2
    drive_gemm<<<hgrid, NT>>>(x, Win0, b0, 64, 0, 256);      // launch 3
    recur_kernel<<<NGRP * NSLC, NTR, smem>>>(W0, 0);         // launch 4 (ncu aim)
    drive_gemm<<<ggrid, NT>>>(x, Win1, b1, 512, 1, 0);
    recur_kernel<<<NGRP * NSLC, NTR, smem>>>(W1, 1);
    drive_gemm<<<ggrid, NT>>>(x, Win2, b2, 512, 2, 0);
    recur_kernel<<<NGRP * NSLC, NTR, smem>>>(W2, 2);
    readout_kernel<<<BB, NT>>>(Wout, bout, out);
}